// round 12
// baseline (speedup 1.0000x reference)
#include <cuda_runtime.h>
#include <math.h>

#define BSZ 64
#define TT  512
#define DA  16
#define DZ  32
#define KK  3
#define GG  12   // 4*H, H=3

// ---------------- scratch (device globals; no allocs allowed) ----------------
__device__ float g_xw0[(size_t)BSZ * TT * GG];
__device__ float g_alpha[(size_t)BSZ * TT * KK];
__device__ float g_muf[(size_t)TT * BSZ * DZ];
__device__ float g_mup[(size_t)TT * BSZ * DZ];
__device__ float g_sigf[(size_t)TT * BSZ * DZ * DZ];
__device__ float g_sigp[(size_t)TT * BSZ * DZ * DZ];

__device__ __forceinline__ float fsigm(float x) {
    return __fdividef(1.0f, 1.0f + __expf(-x));
}
__device__ __forceinline__ float ftanh(float x) {
    x = fminf(fmaxf(x, -10.0f), 10.0f);
    float e = __expf(2.0f * x);
    return __fdividef(e - 1.0f, e + 1.0f);
}

// ---- register/shuffle Gauss-Jordan, row-per-lane, deferred scaling ----
template <int N, int LD>
__device__ __forceinline__ void warp_gj_reg(float* M, int lane) {
    const int i = (N == 32) ? lane : (lane & (N - 1));
    float c[N];
#pragma unroll
    for (int j = 0; j < N; j++) c[j] = M[i * LD + j];
    float dinv = 1.0f;
#pragma unroll
    for (int p = 0; p < N; p++) {
        float pv = __shfl_sync(0xffffffffu, c[p], p);
        float rpv = __fdividef(1.0f, pv);
        float f = (i == p) ? 0.0f : c[p] * rpv;
        if (i == p) dinv = rpv;
        float ncp = (i == p) ? 1.0f : -f;
#pragma unroll
        for (int j = 0; j < N; j++)
            if (j != p) c[j] -= f * __shfl_sync(0xffffffffu, c[j], p);
        c[p] = ncp;
    }
    if (lane < N) {
#pragma unroll
        for (int j = 0; j < N; j++) M[i * LD + j] = c[j] * dinv;
    }
    __syncwarp();
}

// ---------------- Kernel A0: input projection for LSTM layer 0 ----------------
__global__ void xw0_kernel(const float* __restrict__ a,
                           const float* __restrict__ Wih0,
                           const float* __restrict__ bih0,
                           const float* __restrict__ bhh0) {
    int idx = blockIdx.x * blockDim.x + threadIdx.x;
    if (idx >= BSZ * TT * GG) return;
    int j  = idx % GG;
    int bt = idx / GG;
    const float* ar = a + (size_t)bt * DA;
    const float* w  = Wih0 + j * DA;
    float s = bih0[j] + bhh0[j];
#pragma unroll
    for (int d = 0; d < DA; d++) s += ar[d] * w[d];
    g_xw0[idx] = s;
}

// ---------------- Kernel A1: sequential 2-layer LSTM + softmax ----------------
__global__ void lstm_kernel(const float* __restrict__ Whh0,
                            const float* __restrict__ Wih1,
                            const float* __restrict__ Whh1,
                            const float* __restrict__ bih1,
                            const float* __restrict__ bhh1) {
    __shared__ float whh0[GG][3], wih1[GG][3], whh1[GG][3], b1[GG];
    int tid = threadIdx.x;
    if (tid < 36) {
        whh0[tid / 3][tid % 3] = Whh0[tid];
        wih1[tid / 3][tid % 3] = Wih1[tid];
        whh1[tid / 3][tid % 3] = Whh1[tid];
    }
    if (tid < GG) b1[tid] = bih1[tid] + bhh1[tid];
    __syncthreads();

    int b = tid;
    if (b >= BSZ) return;
    float h0[3] = {0, 0, 0}, c0[3] = {0, 0, 0};
    float h1[3] = {0, 0, 0}, c1[3] = {0, 0, 0};
    const float* xw = g_xw0 + (size_t)b * TT * GG;
    float* al = g_alpha + (size_t)b * TT * KK;

    for (int t = 0; t < TT; t++) {
        float g[GG];
#pragma unroll
        for (int j = 0; j < GG; j++)
            g[j] = xw[t * GG + j] + whh0[j][0] * h0[0] + whh0[j][1] * h0[1] + whh0[j][2] * h0[2];
#pragma unroll
        for (int u = 0; u < 3; u++) {
            c0[u] = fsigm(g[3 + u]) * c0[u] + fsigm(g[u]) * ftanh(g[6 + u]);
            h0[u] = fsigm(g[9 + u]) * ftanh(c0[u]);
        }
#pragma unroll
        for (int j = 0; j < GG; j++)
            g[j] = b1[j] + wih1[j][0] * h0[0] + wih1[j][1] * h0[1] + wih1[j][2] * h0[2]
                         + whh1[j][0] * h1[0] + whh1[j][1] * h1[1] + whh1[j][2] * h1[2];
#pragma unroll
        for (int u = 0; u < 3; u++) {
            c1[u] = fsigm(g[3 + u]) * c1[u] + fsigm(g[u]) * ftanh(g[6 + u]);
            h1[u] = fsigm(g[9 + u]) * ftanh(c1[u]);
        }
        float m = fmaxf(h1[0], fmaxf(h1[1], h1[2]));
        float e0 = __expf(h1[0] - m), e1 = __expf(h1[1] - m), e2 = __expf(h1[2] - m);
        float inv = __fdividef(1.0f, e0 + e1 + e2);
        al[t * KK + 0] = e0 * inv;
        al[t * KK + 1] = e1 * inv;
        al[t * KK + 2] = e2 * inv;
    }
}

// ---------------- Kernel B: forward Kalman filter ----------------
// P0 store prefetched mix | P1 r,M1 | P2 S,WT,HT,w | P3 GJ16 || LDG prefetch |
// P4 V,Kg,G | P5 updates.  6 barriers/step. GJ shadow = low-MIO prefetch only.
__global__ void __launch_bounds__(256) fwd_kernel(const float* __restrict__ a,
                                                  const float* __restrict__ A,
                                                  const float* __restrict__ C,
                                                  const float* __restrict__ R,
                                                  const float* __restrict__ Q,
                                                  const float* __restrict__ mu0,
                                                  const float* __restrict__ sigma0) {
    const int b = blockIdx.x;
    const int tid = threadIdx.x;
    const int i8 = tid >> 3;
    const int q4 = (tid & 7) * 4;
    const int lane = tid & 31;

    __shared__ __align__(16) float sAt[DZ][36];
    __shared__ __align__(16) float sCt[DA][36];
    __shared__ __align__(16) float sCtT[DZ][20];
    __shared__ __align__(16) float sSigP[DZ][36], sQ[DZ][36];
    __shared__ __align__(16) float sWT[DZ][36], sV[DZ][36];
    __shared__ __align__(16) float sM1[DZ][20], sKg[DZ][20], sG[DZ][20];
    __shared__ __align__(16) float sM1T[DA][36], sHT[DA][36];
    __shared__ __align__(16) float sS[DA][20];
    __shared__ float sR[DA][17];
    __shared__ float smu_f[DZ], smu_p[DZ], sw[DZ], sr[DA];

    // prefetch registers (workers tid<224 own A-elem tid, plus tid+224 if tid<32;
    // C-elem tid if tid<128)
    float4 pA0 = make_float4(0, 0, 0, 0), pA1 = make_float4(0, 0, 0, 0);
    float4 pC0 = make_float4(0, 0, 0, 0);

    if (tid < DZ) { smu_f[tid] = mu0[tid]; smu_p[tid] = mu0[tid]; }
    {
        int e = tid * 4, ii = e >> 5, jj = e & 31;
        *(float4*)&sSigP[ii][jj] = ((const float4*)sigma0)[tid];
        *(float4*)&sQ[ii][jj]    = ((const float4*)Q)[tid];
        sR[tid >> 4][tid & 15] = R[tid];
    }
    // prologue: mix t=0 directly into smem
    {
        const size_t ab = (size_t)b * TT * KK;
        const float a0 = g_alpha[ab + 0], a1 = g_alpha[ab + 1], a2 = g_alpha[ab + 2];
        const float4* A0 = (const float4*)A;
        const float4* A1 = A0 + (size_t)TT * 256;
        const float4* A2 = A1 + (size_t)TT * 256;
        float4 v0 = A0[tid], v1 = A1[tid], v2 = A2[tid], m;
        m.x = a0 * v0.x + a1 * v1.x + a2 * v2.x;
        m.y = a0 * v0.y + a1 * v1.y + a2 * v2.y;
        m.z = a0 * v0.z + a1 * v1.z + a2 * v2.z;
        m.w = a0 * v0.w + a1 * v1.w + a2 * v2.w;
        int e = tid * 4, ii = e >> 5, jj = e & 31;
        *(float4*)&sAt[ii][jj] = m;
        if (tid < 128) {
            const float4* C0 = (const float4*)C;
            const float4* C1 = C0 + (size_t)TT * 128;
            const float4* C2 = C1 + (size_t)TT * 128;
            float4 w0 = C0[tid], w1 = C1[tid], w2 = C2[tid], c;
            c.x = a0 * w0.x + a1 * w1.x + a2 * w2.x;
            c.y = a0 * w0.y + a1 * w1.y + a2 * w2.y;
            c.z = a0 * w0.z + a1 * w1.z + a2 * w2.z;
            c.w = a0 * w0.w + a1 * w1.w + a2 * w2.w;
            int ec = tid * 4, ic = ec >> 5, jc = ec & 31;
            *(float4*)&sCt[ic][jc] = c;
            sCtT[jc + 0][ic] = c.x; sCtT[jc + 1][ic] = c.y;
            sCtT[jc + 2][ic] = c.z; sCtT[jc + 3][ic] = c.w;
        }
    }
    __syncthreads();

    for (int t = 0; t < TT; t++) {
        // P0 (t>0): store prefetched mixed At/Ct from registers
        if (t > 0) {
            if (tid < 224) {
                int e = tid * 4, ii = e >> 5, jj = e & 31;
                *(float4*)&sAt[ii][jj] = pA0;
                if (tid < 32) {
                    int e2 = (tid + 224) * 4, ii2 = e2 >> 5, jj2 = e2 & 31;
                    *(float4*)&sAt[ii2][jj2] = pA1;
                }
                if (tid < 128) {
                    int ec = tid * 4, ic = ec >> 5, jc = ec & 31;
                    *(float4*)&sCt[ic][jc] = pC0;
                    sCtT[jc + 0][ic] = pC0.x; sCtT[jc + 1][ic] = pC0.y;
                    sCtT[jc + 2][ic] = pC0.z; sCtT[jc + 3][ic] = pC0.w;
                }
            }
            __syncthreads();
        }

        // P1: r = a - Ct mu_f ; M1 = sigP * CtT (+ M1T)
        if (tid < DA) {
            float s = a[((size_t)b * TT + t) * DA + tid];
#pragma unroll
            for (int j = 0; j < DZ; j++) s -= sCt[tid][j] * smu_f[j];
            sr[tid] = s;
        }
        {
            int jj = (tid & 7) * 2;
            float s0 = 0.f, s1 = 0.f;
#pragma unroll
            for (int k = 0; k < DZ; k++) {
                float av = sSigP[i8][k];
                s0 += av * sCtT[k][jj];
                s1 += av * sCtT[k][jj + 1];
            }
            sM1[i8][jj] = s0; sM1[i8][jj + 1] = s1;
            sM1T[jj][i8] = s0; sM1T[jj + 1][i8] = s1;
        }
        __syncthreads();

        // P2: S = Ct*M1 + R ; WT = (At*sigP)^T ; HT = (At*M1)^T ; w = At*mu_p
        {
            if (tid < DA * DA) {
                int i = tid >> 4, j = tid & 15;
                float s = sR[i][j];
#pragma unroll
                for (int k = 0; k < DZ; k++) s += sCt[i][k] * sM1[k][j];
                sS[i][j] = s;
            }
            // WT: 256 float4 outputs over 256 threads
            {
                int row = i8, c4 = q4;
                float4 acc = make_float4(0, 0, 0, 0);
#pragma unroll
                for (int k = 0; k < DZ; k++) {
                    float av = sAt[row][k];
                    float4 bv = *(const float4*)&sSigP[k][c4];
                    acc.x += av * bv.x; acc.y += av * bv.y;
                    acc.z += av * bv.z; acc.w += av * bv.w;
                }
                sWT[c4 + 0][row] = acc.x; sWT[c4 + 1][row] = acc.y;
                sWT[c4 + 2][row] = acc.z; sWT[c4 + 3][row] = acc.w;
            }
            // HT: 512 outputs over 256 threads (2 each)
#pragma unroll
            for (int rep = 0; rep < 2; rep++) {
                int u = tid + rep * 256;
                int i = u >> 4, j = u & 15;
                float h = 0.f;
#pragma unroll
                for (int k = 0; k < DZ; k++) h += sAt[i][k] * sM1[k][j];
                sHT[j][i] = h;
            }
            if (tid < DZ) {
                float s = 0.f;
#pragma unroll
                for (int k = 0; k < DZ; k++) s += sAt[tid][k] * smu_p[k];
                sw[tid] = s;
            }
        }
        __syncthreads();

        // P3: warp 7 inverts S (reg GJ) || workers: LDG-prefetch t+1 A/C mix
        if (tid >= 224) {
            warp_gj_reg<DA, 20>(&sS[0][0], lane);
        } else if (t + 1 < TT) {
            const size_t ab2 = ((size_t)b * TT + (t + 1)) * KK;
            const float na0 = g_alpha[ab2 + 0];
            const float na1 = g_alpha[ab2 + 1];
            const float na2 = g_alpha[ab2 + 2];
            const float4* A0 = (const float4*)A + (size_t)(t + 1) * 256;
            const float4* A1 = A0 + (size_t)TT * 256;
            const float4* A2 = A1 + (size_t)TT * 256;
            {
                float4 v0 = A0[tid], v1 = A1[tid], v2 = A2[tid];
                pA0.x = na0 * v0.x + na1 * v1.x + na2 * v2.x;
                pA0.y = na0 * v0.y + na1 * v1.y + na2 * v2.y;
                pA0.z = na0 * v0.z + na1 * v1.z + na2 * v2.z;
                pA0.w = na0 * v0.w + na1 * v1.w + na2 * v2.w;
            }
            if (tid < 32) {
                float4 v0 = A0[tid + 224], v1 = A1[tid + 224], v2 = A2[tid + 224];
                pA1.x = na0 * v0.x + na1 * v1.x + na2 * v2.x;
                pA1.y = na0 * v0.y + na1 * v1.y + na2 * v2.y;
                pA1.z = na0 * v0.z + na1 * v1.z + na2 * v2.z;
                pA1.w = na0 * v0.w + na1 * v1.w + na2 * v2.w;
            }
            if (tid < 128) {
                const float4* C0 = (const float4*)C + (size_t)(t + 1) * 128;
                const float4* C1 = C0 + (size_t)TT * 128;
                const float4* C2 = C1 + (size_t)TT * 128;
                float4 w0 = C0[tid], w1 = C1[tid], w2 = C2[tid];
                pC0.x = na0 * w0.x + na1 * w1.x + na2 * w2.x;
                pC0.y = na0 * w0.y + na1 * w1.y + na2 * w2.y;
                pC0.z = na0 * w0.z + na1 * w1.z + na2 * w2.z;
                pC0.w = na0 * w0.w + na1 * w1.w + na2 * w2.w;
            }
        }
        __syncthreads();

        // P4: V = At*WT + Q ; Kg = M1*Sinv ; G = H*Sinv
        {
            float4 acc = *(const float4*)&sQ[i8][q4];
#pragma unroll
            for (int k = 0; k < DZ; k++) {
                float av = sAt[i8][k];
                float4 bv = *(const float4*)&sWT[k][q4];
                acc.x += av * bv.x; acc.y += av * bv.y;
                acc.z += av * bv.z; acc.w += av * bv.w;
            }
            *(float4*)&sV[i8][q4] = acc;

            int jj = (tid & 7) * 2;
            float k0 = 0.f, k1 = 0.f, g0 = 0.f, g1 = 0.f;
#pragma unroll
            for (int k = 0; k < DA; k++) {
                float m = sM1[i8][k];
                float h = sHT[k][i8];
                float s0 = sS[k][jj], s1 = sS[k][jj + 1];
                k0 += m * s0; k1 += m * s1;
                g0 += h * s0; g1 += h * s1;
            }
            sKg[i8][jj] = k0; sKg[i8][jj + 1] = k1;
            sG[i8][jj]  = g0; sG[i8][jj + 1]  = g1;
        }
        __syncthreads();

        const size_t sb = (size_t)t * BSZ + b;

        // P5: sigN -> g_sigf ; sigP' = V - G*HT ; mu updates
        {
            float4 accN = *(const float4*)&sSigP[i8][q4];
            float4 accP = *(const float4*)&sV[i8][q4];
#pragma unroll
            for (int k = 0; k < DA; k++) {
                float kg = sKg[i8][k];
                float gg = sG[i8][k];
                float4 m = *(const float4*)&sM1T[k][q4];
                float4 h = *(const float4*)&sHT[k][q4];
                accN.x -= kg * m.x; accN.y -= kg * m.y;
                accN.z -= kg * m.z; accN.w -= kg * m.w;
                accP.x -= gg * h.x; accP.y -= gg * h.y;
                accP.z -= gg * h.z; accP.w -= gg * h.w;
            }
            *(float4*)&g_sigf[sb * (DZ * DZ) + i8 * DZ + q4] = accN;
            *(float4*)&sSigP[i8][q4] = accP;
            *(float4*)&g_sigp[sb * (DZ * DZ) + i8 * DZ + q4] = accP;
        }
        if (tid < DZ) {
            float mn = smu_p[tid];
            float mp = sw[tid];
#pragma unroll
            for (int j = 0; j < DA; j++) {
                mn += sKg[tid][j] * sr[j];
                mp += sG[tid][j] * sr[j];
            }
            smu_f[tid] = mn; g_muf[sb * DZ + tid] = mn;
            smu_p[tid] = mp; g_mup[sb * DZ + tid] = mp;
        }
        __syncthreads();
    }
}

// ---------------- Kernel C: RTS backward smoother ----------------
// P0 U,D,muD | P1 GJ32 || LDG-prefetch next (regs) | P2 J (+store AT) |
// P3 out (+store sigF/sigP next).  4 barriers/step.
__global__ void __launch_bounds__(256) bwd_kernel(const float* __restrict__ A,
                                                  float* __restrict__ out) {
    const int b = blockIdx.x;
    const int tid = threadIdx.x;
    const int i8 = tid >> 3;
    const int q4 = (tid & 7) * 4;
    const int lane = tid & 31;

    __shared__ __align__(16) float sAT[DZ][36];
    __shared__ __align__(16) float sSigF[2][DZ][36];
    __shared__ __align__(16) float sSigNc[DZ][36], sD[DZ][36];
    __shared__ __align__(16) float sU[DZ][36], sJ[DZ][36];
    __shared__ __align__(16) float sP[DZ][36];
    __shared__ float sMuN[DZ], sMuD[DZ];

    // prefetch registers
    float4 pAT0 = make_float4(0, 0, 0, 0), pAT1 = make_float4(0, 0, 0, 0);
    float4 pSF0 = make_float4(0, 0, 0, 0), pSF1 = make_float4(0, 0, 0, 0);
    float4 pSP0 = make_float4(0, 0, 0, 0), pSP1 = make_float4(0, 0, 0, 0);

    // prologue: t=TT-1 output + carry ; load step TT-2 inputs into buffers[0]
    {
        size_t sb = ((size_t)(TT - 1) * BSZ + b);
        size_t ob = ((size_t)b * TT + (TT - 1)) * (DZ + DZ * DZ);
        int e = tid * 4, ii = e >> 5, jj = e & 31;
        float4 v = ((const float4*)(g_sigf + sb * (DZ * DZ)))[tid];
        *(float4*)&sSigNc[ii][jj] = v;
        *(float4*)&out[ob + DZ + e] = v;
        if (tid < DZ) {
            float m = g_muf[sb * DZ + tid];
            sMuN[tid] = m;
            out[ob + tid] = m;
        }
        const int t0 = TT - 2;
        const size_t sb2 = (size_t)t0 * BSZ + b;
        const size_t ab = ((size_t)b * TT + (t0 + 1)) * KK;
        const float a0 = g_alpha[ab + 0], a1 = g_alpha[ab + 1], a2 = g_alpha[ab + 2];
        const float4* A0 = (const float4*)A + (size_t)(t0 + 1) * 256;
        const float4* A1 = A0 + (size_t)TT * 256;
        const float4* A2 = A1 + (size_t)TT * 256;
        float4 v0 = A0[tid], v1 = A1[tid], v2 = A2[tid];
        sAT[jj + 0][ii] = a0 * v0.x + a1 * v1.x + a2 * v2.x;
        sAT[jj + 1][ii] = a0 * v0.y + a1 * v1.y + a2 * v2.y;
        sAT[jj + 2][ii] = a0 * v0.z + a1 * v1.z + a2 * v2.z;
        sAT[jj + 3][ii] = a0 * v0.w + a1 * v1.w + a2 * v2.w;
        *(float4*)&sSigF[0][ii][jj] = ((const float4*)(g_sigf + sb2 * (DZ * DZ)))[tid];
        *(float4*)&sP[ii][jj]       = ((const float4*)(g_sigp + sb2 * (DZ * DZ)))[tid];
    }
    __syncthreads();

    for (int t = TT - 2; t >= 0; t--) {
        const int cur = (TT - 2 - t) & 1;   // current sigF buffer
        const int nxt = cur ^ 1;
        const size_t sb = (size_t)t * BSZ + b;

        // P0: U = sigF*AT ; D = sigNc - sigP ; muD
        {
            float4 acc = make_float4(0, 0, 0, 0);
#pragma unroll
            for (int k = 0; k < DZ; k++) {
                float av = sSigF[cur][i8][k];
                float4 bv = *(const float4*)&sAT[k][q4];
                acc.x += av * bv.x; acc.y += av * bv.y;
                acc.z += av * bv.z; acc.w += av * bv.w;
            }
            *(float4*)&sU[i8][q4] = acc;
            float4 n = *(const float4*)&sSigNc[i8][q4];
            float4 p4 = *(const float4*)&sP[i8][q4];
            float4 d = make_float4(n.x - p4.x, n.y - p4.y, n.z - p4.z, n.w - p4.w);
            *(float4*)&sD[i8][q4] = d;
            if (tid < DZ) sMuD[tid] = sMuN[tid] - g_mup[sb * DZ + tid];
        }
        __syncthreads();

        // P1: warp 7 inverts sigP (reg GJ) || workers: LDG-prefetch t-1 inputs
        if (tid >= 224) {
            warp_gj_reg<DZ, 36>(&sP[0][0], lane);
        } else if (t > 0) {
            const int t2 = t - 1;
            const size_t sb2 = (size_t)t2 * BSZ + b;
            const size_t ab2 = ((size_t)b * TT + (t2 + 1)) * KK;
            const float na0 = g_alpha[ab2 + 0];
            const float na1 = g_alpha[ab2 + 1];
            const float na2 = g_alpha[ab2 + 2];
            const float4* A0 = (const float4*)A + (size_t)(t2 + 1) * 256;
            const float4* A1 = A0 + (size_t)TT * 256;
            const float4* A2 = A1 + (size_t)TT * 256;
            {
                float4 v0 = A0[tid], v1 = A1[tid], v2 = A2[tid];
                pAT0.x = na0 * v0.x + na1 * v1.x + na2 * v2.x;
                pAT0.y = na0 * v0.y + na1 * v1.y + na2 * v2.y;
                pAT0.z = na0 * v0.z + na1 * v1.z + na2 * v2.z;
                pAT0.w = na0 * v0.w + na1 * v1.w + na2 * v2.w;
                pSF0 = ((const float4*)(g_sigf + sb2 * (DZ * DZ)))[tid];
                pSP0 = ((const float4*)(g_sigp + sb2 * (DZ * DZ)))[tid];
            }
            if (tid < 32) {
                int u = tid + 224;
                float4 v0 = A0[u], v1 = A1[u], v2 = A2[u];
                pAT1.x = na0 * v0.x + na1 * v1.x + na2 * v2.x;
                pAT1.y = na0 * v0.y + na1 * v1.y + na2 * v2.y;
                pAT1.z = na0 * v0.z + na1 * v1.z + na2 * v2.z;
                pAT1.w = na0 * v0.w + na1 * v1.w + na2 * v2.w;
                pSF1 = ((const float4*)(g_sigf + sb2 * (DZ * DZ)))[u];
                pSP1 = ((const float4*)(g_sigp + sb2 * (DZ * DZ)))[u];
            }
        }
        __syncthreads();

        // P2: J = U * Pinv ; workers scatter-store prefetched AT (sAT dead)
        {
            float4 acc = make_float4(0, 0, 0, 0);
#pragma unroll
            for (int k = 0; k < DZ; k++) {
                float av = sU[i8][k];
                float4 bv = *(const float4*)&sP[k][q4];
                acc.x += av * bv.x; acc.y += av * bv.y;
                acc.z += av * bv.z; acc.w += av * bv.w;
            }
            *(float4*)&sJ[i8][q4] = acc;
        }
        if (t > 0 && tid < 224) {
            int e = tid * 4, ii = e >> 5, jj = e & 31;
            sAT[jj + 0][ii] = pAT0.x; sAT[jj + 1][ii] = pAT0.y;
            sAT[jj + 2][ii] = pAT0.z; sAT[jj + 3][ii] = pAT0.w;
            if (tid < 32) {
                int e2 = (tid + 224) * 4, ii2 = e2 >> 5, jj2 = e2 & 31;
                sAT[jj2 + 0][ii2] = pAT1.x; sAT[jj2 + 1][ii2] = pAT1.y;
                sAT[jj2 + 2][ii2] = pAT1.z; sAT[jj2 + 3][ii2] = pAT1.w;
            }
        }
        __syncthreads();

        // P3: sigS = sigF + J*D -> out + carry ; muS ; store prefetched sigF/sigP
        {
            const size_t ob = ((size_t)b * TT + t) * (DZ + DZ * DZ);
            float4 acc = *(const float4*)&sSigF[cur][i8][q4];
#pragma unroll
            for (int k = 0; k < DZ; k++) {
                float av = sJ[i8][k];
                float4 bv = *(const float4*)&sD[k][q4];
                acc.x += av * bv.x; acc.y += av * bv.y;
                acc.z += av * bv.z; acc.w += av * bv.w;
            }
            *(float4*)&sSigNc[i8][q4] = acc;
            *(float4*)&out[ob + DZ + i8 * DZ + q4] = acc;
            if (tid < DZ) {
                float s = g_muf[sb * DZ + tid];
#pragma unroll
                for (int k = 0; k < DZ; k++) s += sJ[tid][k] * sMuD[k];
                sMuN[tid] = s;
                out[ob + tid] = s;
            }
        }
        if (t > 0 && tid < 224) {
            int e = tid * 4, ii = e >> 5, jj = e & 31;
            *(float4*)&sSigF[nxt][ii][jj] = pSF0;
            *(float4*)&sP[ii][jj] = pSP0;
            if (tid < 32) {
                int e2 = (tid + 224) * 4, ii2 = e2 >> 5, jj2 = e2 & 31;
                *(float4*)&sSigF[nxt][ii2][jj2] = pSF1;
                *(float4*)&sP[ii2][jj2] = pSP1;
            }
        }
        __syncthreads();
    }
}

// ---------------- launch ----------------
extern "C" void kernel_launch(void* const* d_in, const int* in_sizes, int n_in,
                              void* d_out, int out_size) {
    const float* a      = (const float*)d_in[0];
    const float* A      = (const float*)d_in[1];
    const float* C      = (const float*)d_in[2];
    const float* R      = (const float*)d_in[3];
    const float* Q      = (const float*)d_in[4];
    const float* mu0    = (const float*)d_in[5];
    const float* sigma0 = (const float*)d_in[6];
    const float* Wih0   = (const float*)d_in[7];
    const float* Whh0   = (const float*)d_in[8];
    const float* bih0   = (const float*)d_in[9];
    const float* bhh0   = (const float*)d_in[10];
    const float* Wih1   = (const float*)d_in[11];
    const float* Whh1   = (const float*)d_in[12];
    const float* bih1   = (const float*)d_in[13];
    const float* bhh1   = (const float*)d_in[14];
    float* out = (float*)d_out;

    int n0 = BSZ * TT * GG;
    xw0_kernel<<<(n0 + 255) / 256, 256>>>(a, Wih0, bih0, bhh0);
    lstm_kernel<<<1, 64>>>(Whh0, Wih1, Whh1, bih1, bhh1);
    fwd_kernel<<<BSZ, 256>>>(a, A, C, R, Q, mu0, sigma0);
    bwd_kernel<<<BSZ, 256>>>(A, out);
}

// round 13
// speedup vs baseline: 1.9406x; 1.9406x over previous
#include <cuda_runtime.h>
#include <math.h>

#define BSZ 64
#define TT  512
#define DA  16
#define DZ  32
#define KK  3
#define GG  12   // 4*H, H=3

// ---------------- scratch (device globals; no allocs allowed) ----------------
__device__ float g_xw0[(size_t)BSZ * TT * GG];
__device__ float g_alpha[(size_t)BSZ * TT * KK];
__device__ float g_muf[(size_t)TT * BSZ * DZ];
__device__ float g_mup[(size_t)TT * BSZ * DZ];
__device__ float g_sigf[(size_t)TT * BSZ * DZ * DZ];   // 128 MiB
__device__ float g_sigp[(size_t)TT * BSZ * DZ * DZ];   // 128 MiB
__device__ float g_pinv[(size_t)TT * BSZ * DZ * DZ];   // 128 MiB (sigp^-1)

__device__ __forceinline__ float fsigm(float x) {
    return __fdividef(1.0f, 1.0f + __expf(-x));
}
__device__ __forceinline__ float ftanh(float x) {
    x = fminf(fmaxf(x, -10.0f), 10.0f);
    float e = __expf(2.0f * x);
    return __fdividef(e - 1.0f, e + 1.0f);
}

// ---- register/shuffle Gauss-Jordan on smem, row-per-lane, deferred scaling ----
template <int N, int LD>
__device__ __forceinline__ void warp_gj_reg(float* M, int lane) {
    const int i = (N == 32) ? lane : (lane & (N - 1));
    float c[N];
#pragma unroll
    for (int j = 0; j < N; j++) c[j] = M[i * LD + j];
    float dinv = 1.0f;
#pragma unroll
    for (int p = 0; p < N; p++) {
        float pv = __shfl_sync(0xffffffffu, c[p], p);
        float rpv = __fdividef(1.0f, pv);
        float f = (i == p) ? 0.0f : c[p] * rpv;
        if (i == p) dinv = rpv;
        float ncp = (i == p) ? 1.0f : -f;
#pragma unroll
        for (int j = 0; j < N; j++)
            if (j != p) c[j] -= f * __shfl_sync(0xffffffffu, c[j], p);
        c[p] = ncp;
    }
    if (lane < N) {
#pragma unroll
        for (int j = 0; j < N; j++) M[i * LD + j] = c[j] * dinv;
    }
    __syncwarp();
}

// ---------------- Kernel A0: input projection for LSTM layer 0 ----------------
__global__ void xw0_kernel(const float* __restrict__ a,
                           const float* __restrict__ Wih0,
                           const float* __restrict__ bih0,
                           const float* __restrict__ bhh0) {
    int idx = blockIdx.x * blockDim.x + threadIdx.x;
    if (idx >= BSZ * TT * GG) return;
    int j  = idx % GG;
    int bt = idx / GG;
    const float* ar = a + (size_t)bt * DA;
    const float* w  = Wih0 + j * DA;
    float s = bih0[j] + bhh0[j];
#pragma unroll
    for (int d = 0; d < DA; d++) s += ar[d] * w[d];
    g_xw0[idx] = s;
}

// ---------------- Kernel A1: sequential 2-layer LSTM + softmax ----------------
__global__ void lstm_kernel(const float* __restrict__ Whh0,
                            const float* __restrict__ Wih1,
                            const float* __restrict__ Whh1,
                            const float* __restrict__ bih1,
                            const float* __restrict__ bhh1) {
    __shared__ float whh0[GG][3], wih1[GG][3], whh1[GG][3], b1[GG];
    int tid = threadIdx.x;
    if (tid < 36) {
        whh0[tid / 3][tid % 3] = Whh0[tid];
        wih1[tid / 3][tid % 3] = Wih1[tid];
        whh1[tid / 3][tid % 3] = Whh1[tid];
    }
    if (tid < GG) b1[tid] = bih1[tid] + bhh1[tid];
    __syncthreads();

    int b = tid;
    if (b >= BSZ) return;
    float h0[3] = {0, 0, 0}, c0[3] = {0, 0, 0};
    float h1[3] = {0, 0, 0}, c1[3] = {0, 0, 0};
    const float* xw = g_xw0 + (size_t)b * TT * GG;
    float* al = g_alpha + (size_t)b * TT * KK;

    for (int t = 0; t < TT; t++) {
        float g[GG];
#pragma unroll
        for (int j = 0; j < GG; j++)
            g[j] = xw[t * GG + j] + whh0[j][0] * h0[0] + whh0[j][1] * h0[1] + whh0[j][2] * h0[2];
#pragma unroll
        for (int u = 0; u < 3; u++) {
            c0[u] = fsigm(g[3 + u]) * c0[u] + fsigm(g[u]) * ftanh(g[6 + u]);
            h0[u] = fsigm(g[9 + u]) * ftanh(c0[u]);
        }
#pragma unroll
        for (int j = 0; j < GG; j++)
            g[j] = b1[j] + wih1[j][0] * h0[0] + wih1[j][1] * h0[1] + wih1[j][2] * h0[2]
                         + whh1[j][0] * h1[0] + whh1[j][1] * h1[1] + whh1[j][2] * h1[2];
#pragma unroll
        for (int u = 0; u < 3; u++) {
            c1[u] = fsigm(g[3 + u]) * c1[u] + fsigm(g[u]) * ftanh(g[6 + u]);
            h1[u] = fsigm(g[9 + u]) * ftanh(c1[u]);
        }
        float m = fmaxf(h1[0], fmaxf(h1[1], h1[2]));
        float e0 = __expf(h1[0] - m), e1 = __expf(h1[1] - m), e2 = __expf(h1[2] - m);
        float inv = __fdividef(1.0f, e0 + e1 + e2);
        al[t * KK + 0] = e0 * inv;
        al[t * KK + 1] = e1 * inv;
        al[t * KK + 2] = e2 * inv;
    }
}

// ---------------- Kernel B: forward Kalman filter ----------------
// P0 mix | P1 r,M1,M1T | P2 S,WT,HT,w | P3 GJ16 (warp 0, serial) |
// P4 V,Kg,G | P5 updates.  6 barriers/step.
__global__ void __launch_bounds__(256) fwd_kernel(const float* __restrict__ a,
                                                  const float* __restrict__ A,
                                                  const float* __restrict__ C,
                                                  const float* __restrict__ R,
                                                  const float* __restrict__ Q,
                                                  const float* __restrict__ mu0,
                                                  const float* __restrict__ sigma0) {
    const int b = blockIdx.x;
    const int tid = threadIdx.x;
    const int i8 = tid >> 3;
    const int q4 = (tid & 7) * 4;

    __shared__ __align__(16) float sAt[DZ][36];
    __shared__ __align__(16) float sCt[DA][36];
    __shared__ __align__(16) float sCtT[DZ][20];
    __shared__ __align__(16) float sSigP[DZ][36], sQ[DZ][36];
    __shared__ __align__(16) float sWT[DZ][36], sV[DZ][36];
    __shared__ __align__(16) float sM1[DZ][20], sKg[DZ][20], sG[DZ][20];
    __shared__ __align__(16) float sM1T[DA][36], sHT[DA][36];
    __shared__ __align__(16) float sS[DA][20];
    __shared__ float sR[DA][17];
    __shared__ float smu_f[DZ], smu_p[DZ], sw[DZ], sr[DA];

    if (tid < DZ) { smu_f[tid] = mu0[tid]; smu_p[tid] = mu0[tid]; }
    {
        int e = tid * 4, ii = e >> 5, jj = e & 31;
        *(float4*)&sSigP[ii][jj] = ((const float4*)sigma0)[tid];
        *(float4*)&sQ[ii][jj]    = ((const float4*)Q)[tid];
        sR[tid >> 4][tid & 15] = R[tid];
    }
    __syncthreads();

    for (int t = 0; t < TT; t++) {
        // P0: mix At, Ct (+ CtT) from global
        const size_t abase = ((size_t)b * TT + t) * KK;
        const float a0 = g_alpha[abase + 0];
        const float a1 = g_alpha[abase + 1];
        const float a2 = g_alpha[abase + 2];
        {
            const float4* A0 = (const float4*)A + (size_t)t * 256;
            const float4* A1 = A0 + (size_t)TT * 256;
            const float4* A2 = A1 + (size_t)TT * 256;
            float4 v0 = A0[tid], v1 = A1[tid], v2 = A2[tid], m;
            m.x = a0 * v0.x + a1 * v1.x + a2 * v2.x;
            m.y = a0 * v0.y + a1 * v1.y + a2 * v2.y;
            m.z = a0 * v0.z + a1 * v1.z + a2 * v2.z;
            m.w = a0 * v0.w + a1 * v1.w + a2 * v2.w;
            int e = tid * 4, ii = e >> 5, jj = e & 31;
            *(float4*)&sAt[ii][jj] = m;
            if (tid < 128) {
                const float4* C0 = (const float4*)C + (size_t)t * 128;
                const float4* C1 = C0 + (size_t)TT * 128;
                const float4* C2 = C1 + (size_t)TT * 128;
                float4 w0 = C0[tid], w1 = C1[tid], w2 = C2[tid], c;
                c.x = a0 * w0.x + a1 * w1.x + a2 * w2.x;
                c.y = a0 * w0.y + a1 * w1.y + a2 * w2.y;
                c.z = a0 * w0.z + a1 * w1.z + a2 * w2.z;
                c.w = a0 * w0.w + a1 * w1.w + a2 * w2.w;
                int ec = tid * 4, ic = ec >> 5, jc = ec & 31;
                *(float4*)&sCt[ic][jc] = c;
                sCtT[jc + 0][ic] = c.x; sCtT[jc + 1][ic] = c.y;
                sCtT[jc + 2][ic] = c.z; sCtT[jc + 3][ic] = c.w;
            }
        }
        __syncthreads();

        // P1: r = a - Ct mu_f ; M1 = sigP * CtT (+ M1T)
        if (tid < DA) {
            float s = a[((size_t)b * TT + t) * DA + tid];
#pragma unroll
            for (int j = 0; j < DZ; j++) s -= sCt[tid][j] * smu_f[j];
            sr[tid] = s;
        }
        {
            int jj = (tid & 7) * 2;
            float s0 = 0.f, s1 = 0.f;
#pragma unroll
            for (int k = 0; k < DZ; k++) {
                float av = sSigP[i8][k];
                s0 += av * sCtT[k][jj];
                s1 += av * sCtT[k][jj + 1];
            }
            sM1[i8][jj] = s0; sM1[i8][jj + 1] = s1;
            sM1T[jj][i8] = s0; sM1T[jj + 1][i8] = s1;
        }
        __syncthreads();

        // P2: S = Ct*M1 + R ; WT = (At*sigP)^T ; HT = (At*M1)^T ; w = At*mu_p
        {
            {
                int i = tid >> 4, j = tid & 15;
                float s = sR[i][j];
#pragma unroll
                for (int k = 0; k < DZ; k++) s += sCt[i][k] * sM1[k][j];
                sS[i][j] = s;
            }
            {
                float4 acc = make_float4(0, 0, 0, 0);
#pragma unroll
                for (int k = 0; k < DZ; k++) {
                    float av = sAt[i8][k];
                    float4 bv = *(const float4*)&sSigP[k][q4];
                    acc.x += av * bv.x; acc.y += av * bv.y;
                    acc.z += av * bv.z; acc.w += av * bv.w;
                }
                sWT[q4 + 0][i8] = acc.x; sWT[q4 + 1][i8] = acc.y;
                sWT[q4 + 2][i8] = acc.z; sWT[q4 + 3][i8] = acc.w;
            }
#pragma unroll
            for (int rep = 0; rep < 2; rep++) {
                int u = tid + rep * 256;
                int i = u >> 4, j = u & 15;
                float h = 0.f;
#pragma unroll
                for (int k = 0; k < DZ; k++) h += sAt[i][k] * sM1[k][j];
                sHT[j][i] = h;
            }
            if (tid < DZ) {
                float s = 0.f;
#pragma unroll
                for (int k = 0; k < DZ; k++) s += sAt[tid][k] * smu_p[k];
                sw[tid] = s;
            }
        }
        __syncthreads();

        // P3: warp 0 inverts S in place (serial; everyone else waits)
        if (tid < 32) warp_gj_reg<DA, 20>(&sS[0][0], tid);
        __syncthreads();

        // P4: V = At*WT + Q ; Kg = M1*Sinv ; G = H*Sinv
        {
            float4 acc = *(const float4*)&sQ[i8][q4];
#pragma unroll
            for (int k = 0; k < DZ; k++) {
                float av = sAt[i8][k];
                float4 bv = *(const float4*)&sWT[k][q4];
                acc.x += av * bv.x; acc.y += av * bv.y;
                acc.z += av * bv.z; acc.w += av * bv.w;
            }
            *(float4*)&sV[i8][q4] = acc;

            int jj = (tid & 7) * 2;
            float k0 = 0.f, k1 = 0.f, g0 = 0.f, g1 = 0.f;
#pragma unroll
            for (int k = 0; k < DA; k++) {
                float m = sM1[i8][k];
                float h = sHT[k][i8];
                float s0 = sS[k][jj], s1 = sS[k][jj + 1];
                k0 += m * s0; k1 += m * s1;
                g0 += h * s0; g1 += h * s1;
            }
            sKg[i8][jj] = k0; sKg[i8][jj + 1] = k1;
            sG[i8][jj]  = g0; sG[i8][jj + 1]  = g1;
        }
        __syncthreads();

        const size_t sb = (size_t)t * BSZ + b;

        // P5: sigN = sigP - Kg*M1T -> g_sigf ; sigP' = V - G*HT -> sSigP/g_sigp;
        //     mu_new = mu_p + Kg r ; mu_p' = w + G r
        {
            float4 accN = *(const float4*)&sSigP[i8][q4];
            float4 accP = *(const float4*)&sV[i8][q4];
#pragma unroll
            for (int k = 0; k < DA; k++) {
                float kg = sKg[i8][k];
                float gg = sG[i8][k];
                float4 m = *(const float4*)&sM1T[k][q4];
                float4 h = *(const float4*)&sHT[k][q4];
                accN.x -= kg * m.x; accN.y -= kg * m.y;
                accN.z -= kg * m.z; accN.w -= kg * m.w;
                accP.x -= gg * h.x; accP.y -= gg * h.y;
                accP.z -= gg * h.z; accP.w -= gg * h.w;
            }
            *(float4*)&g_sigf[sb * (DZ * DZ) + i8 * DZ + q4] = accN;
            *(float4*)&sSigP[i8][q4] = accP;
            *(float4*)&g_sigp[sb * (DZ * DZ) + i8 * DZ + q4] = accP;
        }
        if (tid < DZ) {
            float mn = smu_p[tid];
            float mp = sw[tid];
#pragma unroll
            for (int j = 0; j < DA; j++) {
                mn += sKg[tid][j] * sr[j];
                mp += sG[tid][j] * sr[j];
            }
            smu_f[tid] = mn; g_muf[sb * DZ + tid] = mn;
            smu_p[tid] = mp; g_mup[sb * DZ + tid] = mp;
        }
        __syncthreads();
    }
}

// ---------------- Kernel I: batch-parallel inversion of all sigp_t ----------
// One warp per 32x32 matrix; rows in registers, shuffle GJ; fully parallel.
__global__ void __launch_bounds__(256) inv_kernel() {
    const int w = blockIdx.x * (blockDim.x >> 5) + (threadIdx.x >> 5);
    if (w >= TT * BSZ) return;
    const int lane = threadIdx.x & 31;

    const float4* src = (const float4*)(g_sigp + (size_t)w * (DZ * DZ));
    float c[DZ];
#pragma unroll
    for (int s = 0; s < 8; s++) {
        float4 v = src[lane * 8 + s];
        c[s * 4 + 0] = v.x; c[s * 4 + 1] = v.y;
        c[s * 4 + 2] = v.z; c[s * 4 + 3] = v.w;
    }
    float dinv = 1.0f;
#pragma unroll
    for (int p = 0; p < DZ; p++) {
        float pv = __shfl_sync(0xffffffffu, c[p], p);
        float rpv = __fdividef(1.0f, pv);
        float f = (lane == p) ? 0.0f : c[p] * rpv;
        if (lane == p) dinv = rpv;
        float ncp = (lane == p) ? 1.0f : -f;
#pragma unroll
        for (int j = 0; j < DZ; j++)
            if (j != p) c[j] -= f * __shfl_sync(0xffffffffu, c[j], p);
        c[p] = ncp;
    }
    float4* dst = (float4*)(g_pinv + (size_t)w * (DZ * DZ));
#pragma unroll
    for (int s = 0; s < 8; s++) {
        float4 v;
        v.x = c[s * 4 + 0] * dinv; v.y = c[s * 4 + 1] * dinv;
        v.z = c[s * 4 + 2] * dinv; v.w = c[s * 4 + 3] * dinv;
        dst[lane * 8 + s] = v;
    }
}

// ---------------- Kernel C: RTS backward smoother (no inversions) ----------
// sigS = sigF + U*(Pinv*D), muS = muF + U*(Pinv*muD), U = sigF*A^T.
// P0 mix/load/D/muD | P1 U, X=Pinv*D, xv=Pinv*muD | P2 outputs.  3 barriers.
__global__ void __launch_bounds__(256) bwd_kernel(const float* __restrict__ A,
                                                  float* __restrict__ out) {
    const int b = blockIdx.x;
    const int tid = threadIdx.x;
    const int i8 = tid >> 3;
    const int q4 = (tid & 7) * 4;

    __shared__ __align__(16) float sAT[DZ][36];
    __shared__ __align__(16) float sSigF[DZ][36], sSigNc[DZ][36], sD[DZ][36];
    __shared__ __align__(16) float sU[DZ][36], sX[DZ][36], sPinv[DZ][36];
    __shared__ float sMuN[DZ], sMuD[DZ], sxv[DZ];

    // prologue: t = TT-1 (smoothed == filtered)
    {
        size_t sb = ((size_t)(TT - 1) * BSZ + b);
        size_t ob = ((size_t)b * TT + (TT - 1)) * (DZ + DZ * DZ);
        int e = tid * 4, ii = e >> 5, jj = e & 31;
        float4 v = ((const float4*)(g_sigf + sb * (DZ * DZ)))[tid];
        *(float4*)&sSigNc[ii][jj] = v;
        *(float4*)&out[ob + DZ + e] = v;
        if (tid < DZ) {
            float m = g_muf[sb * DZ + tid];
            sMuN[tid] = m;
            out[ob + tid] = m;
        }
    }
    __syncthreads();

    for (int t = TT - 2; t >= 0; t--) {
        const size_t sb = (size_t)t * BSZ + b;
        const size_t abase = ((size_t)b * TT + (t + 1)) * KK;
        const float a0 = g_alpha[abase + 0];
        const float a1 = g_alpha[abase + 1];
        const float a2 = g_alpha[abase + 2];

        // P0: mix A^T ; load sigF, Pinv ; D = sigNc - sigP ; muD
        {
            const float4* A0 = (const float4*)A + (size_t)(t + 1) * 256;
            const float4* A1 = A0 + (size_t)TT * 256;
            const float4* A2 = A1 + (size_t)TT * 256;
            float4 v0 = A0[tid], v1 = A1[tid], v2 = A2[tid];
            int e = tid * 4, ii = e >> 5, jj = e & 31;
            sAT[jj + 0][ii] = a0 * v0.x + a1 * v1.x + a2 * v2.x;
            sAT[jj + 1][ii] = a0 * v0.y + a1 * v1.y + a2 * v2.y;
            sAT[jj + 2][ii] = a0 * v0.z + a1 * v1.z + a2 * v2.z;
            sAT[jj + 3][ii] = a0 * v0.w + a1 * v1.w + a2 * v2.w;

            float4 sf = ((const float4*)(g_sigf + sb * (DZ * DZ)))[tid];
            *(float4*)&sSigF[ii][jj] = sf;
            float4 pi = ((const float4*)(g_pinv + sb * (DZ * DZ)))[tid];
            *(float4*)&sPinv[ii][jj] = pi;
            float4 sp = ((const float4*)(g_sigp + sb * (DZ * DZ)))[tid];
            float4 d;
            d.x = sSigNc[ii][jj + 0] - sp.x;
            d.y = sSigNc[ii][jj + 1] - sp.y;
            d.z = sSigNc[ii][jj + 2] - sp.z;
            d.w = sSigNc[ii][jj + 3] - sp.w;
            *(float4*)&sD[ii][jj] = d;
            if (tid < DZ) sMuD[tid] = sMuN[tid] - g_mup[sb * DZ + tid];
        }
        __syncthreads();

        // P1: U = sigF*AT ; X = Pinv*D ; xv = Pinv*muD
        {
            float4 au = make_float4(0, 0, 0, 0);
            float4 ax = make_float4(0, 0, 0, 0);
#pragma unroll
            for (int k = 0; k < DZ; k++) {
                float fu = sSigF[i8][k];
                float fx = sPinv[i8][k];
                float4 bu = *(const float4*)&sAT[k][q4];
                float4 bx = *(const float4*)&sD[k][q4];
                au.x += fu * bu.x; au.y += fu * bu.y;
                au.z += fu * bu.z; au.w += fu * bu.w;
                ax.x += fx * bx.x; ax.y += fx * bx.y;
                ax.z += fx * bx.z; ax.w += fx * bx.w;
            }
            *(float4*)&sU[i8][q4] = au;
            *(float4*)&sX[i8][q4] = ax;
            if (tid < DZ) {
                float s = 0.f;
#pragma unroll
                for (int k = 0; k < DZ; k++) s += sPinv[tid][k] * sMuD[k];
                sxv[tid] = s;
            }
        }
        __syncthreads();

        // P2: sigS = sigF + U*X -> out + carry ; muS = muF + U*xv -> out + carry
        {
            const size_t ob = ((size_t)b * TT + t) * (DZ + DZ * DZ);
            float4 acc = *(const float4*)&sSigF[i8][q4];
#pragma unroll
            for (int k = 0; k < DZ; k++) {
                float av = sU[i8][k];
                float4 bv = *(const float4*)&sX[k][q4];
                acc.x += av * bv.x; acc.y += av * bv.y;
                acc.z += av * bv.z; acc.w += av * bv.w;
            }
            *(float4*)&sSigNc[i8][q4] = acc;
            *(float4*)&out[ob + DZ + i8 * DZ + q4] = acc;
            if (tid < DZ) {
                float s = g_muf[sb * DZ + tid];
#pragma unroll
                for (int k = 0; k < DZ; k++) s += sU[tid][k] * sxv[k];
                sMuN[tid] = s;
                out[ob + tid] = s;
            }
        }
        __syncthreads();
    }
}

// ---------------- launch ----------------
extern "C" void kernel_launch(void* const* d_in, const int* in_sizes, int n_in,
                              void* d_out, int out_size) {
    const float* a      = (const float*)d_in[0];
    const float* A      = (const float*)d_in[1];
    const float* C      = (const float*)d_in[2];
    const float* R      = (const float*)d_in[3];
    const float* Q      = (const float*)d_in[4];
    const float* mu0    = (const float*)d_in[5];
    const float* sigma0 = (const float*)d_in[6];
    const float* Wih0   = (const float*)d_in[7];
    const float* Whh0   = (const float*)d_in[8];
    const float* bih0   = (const float*)d_in[9];
    const float* bhh0   = (const float*)d_in[10];
    const float* Wih1   = (const float*)d_in[11];
    const float* Whh1   = (const float*)d_in[12];
    const float* bih1   = (const float*)d_in[13];
    const float* bhh1   = (const float*)d_in[14];
    float* out = (float*)d_out;

    int n0 = BSZ * TT * GG;
    xw0_kernel<<<(n0 + 255) / 256, 256>>>(a, Wih0, bih0, bhh0);
    lstm_kernel<<<1, 64>>>(Whh0, Wih1, Whh1, bih1, bhh1);
    fwd_kernel<<<BSZ, 256>>>(a, A, C, R, Q, mu0, sigma0);
    inv_kernel<<<(TT * BSZ) / 8, 256>>>();
    bwd_kernel<<<BSZ, 256>>>(A, out);
}

// round 14
// speedup vs baseline: 1.9940x; 1.0275x over previous
#include <cuda_runtime.h>
#include <math.h>

#define BSZ 64
#define TT  512
#define DA  16
#define DZ  32
#define KK  3
#define GG  12   // 4*H, H=3

// ---------------- scratch (device globals; no allocs allowed) ----------------
__device__ float g_xw0[(size_t)BSZ * TT * GG];
__device__ float g_alpha[(size_t)BSZ * TT * KK];
__device__ float g_muf[(size_t)TT * BSZ * DZ];
__device__ float g_mup[(size_t)TT * BSZ * DZ];
__device__ float g_sigf[(size_t)TT * BSZ * DZ * DZ];   // 128 MiB
__device__ float g_sigp[(size_t)TT * BSZ * DZ * DZ];   // 128 MiB
__device__ float g_pinv[(size_t)TT * BSZ * DZ * DZ];   // 128 MiB (sigp^-1)

__device__ __forceinline__ float fsigm(float x) {
    return __fdividef(1.0f, 1.0f + __expf(-x));
}
__device__ __forceinline__ float ftanh(float x) {
    x = fminf(fmaxf(x, -10.0f), 10.0f);
    float e = __expf(2.0f * x);
    return __fdividef(e - 1.0f, e + 1.0f);
}

// ---- register/shuffle Gauss-Jordan on smem, row-per-lane, deferred scaling ----
template <int N, int LD>
__device__ __forceinline__ void warp_gj_reg(float* M, int lane) {
    const int i = (N == 32) ? lane : (lane & (N - 1));
    float c[N];
#pragma unroll
    for (int j = 0; j < N; j++) c[j] = M[i * LD + j];
    float dinv = 1.0f;
#pragma unroll
    for (int p = 0; p < N; p++) {
        float pv = __shfl_sync(0xffffffffu, c[p], p);
        float rpv = __fdividef(1.0f, pv);
        float f = (i == p) ? 0.0f : c[p] * rpv;
        if (i == p) dinv = rpv;
        float ncp = (i == p) ? 1.0f : -f;
#pragma unroll
        for (int j = 0; j < N; j++)
            if (j != p) c[j] -= f * __shfl_sync(0xffffffffu, c[j], p);
        c[p] = ncp;
    }
    if (lane < N) {
#pragma unroll
        for (int j = 0; j < N; j++) M[i * LD + j] = c[j] * dinv;
    }
    __syncwarp();
}

// ---------------- Kernel A0: input projection for LSTM layer 0 ----------------
__global__ void xw0_kernel(const float* __restrict__ a,
                           const float* __restrict__ Wih0,
                           const float* __restrict__ bih0,
                           const float* __restrict__ bhh0) {
    int idx = blockIdx.x * blockDim.x + threadIdx.x;
    if (idx >= BSZ * TT * GG) return;
    int j  = idx % GG;
    int bt = idx / GG;
    const float* ar = a + (size_t)bt * DA;
    const float* w  = Wih0 + j * DA;
    float s = bih0[j] + bhh0[j];
#pragma unroll
    for (int d = 0; d < DA; d++) s += ar[d] * w[d];
    g_xw0[idx] = s;
}

// ---------------- Kernel A1: sequential 2-layer LSTM + softmax ----------------
__global__ void lstm_kernel(const float* __restrict__ Whh0,
                            const float* __restrict__ Wih1,
                            const float* __restrict__ Whh1,
                            const float* __restrict__ bih1,
                            const float* __restrict__ bhh1) {
    __shared__ float whh0[GG][3], wih1[GG][3], whh1[GG][3], b1[GG];
    int tid = threadIdx.x;
    if (tid < 36) {
        whh0[tid / 3][tid % 3] = Whh0[tid];
        wih1[tid / 3][tid % 3] = Wih1[tid];
        whh1[tid / 3][tid % 3] = Whh1[tid];
    }
    if (tid < GG) b1[tid] = bih1[tid] + bhh1[tid];
    __syncthreads();

    int b = tid;
    if (b >= BSZ) return;
    float h0[3] = {0, 0, 0}, c0[3] = {0, 0, 0};
    float h1[3] = {0, 0, 0}, c1[3] = {0, 0, 0};
    const float* xw = g_xw0 + (size_t)b * TT * GG;
    float* al = g_alpha + (size_t)b * TT * KK;

    for (int t = 0; t < TT; t++) {
        float g[GG];
#pragma unroll
        for (int j = 0; j < GG; j++)
            g[j] = xw[t * GG + j] + whh0[j][0] * h0[0] + whh0[j][1] * h0[1] + whh0[j][2] * h0[2];
#pragma unroll
        for (int u = 0; u < 3; u++) {
            c0[u] = fsigm(g[3 + u]) * c0[u] + fsigm(g[u]) * ftanh(g[6 + u]);
            h0[u] = fsigm(g[9 + u]) * ftanh(c0[u]);
        }
#pragma unroll
        for (int j = 0; j < GG; j++)
            g[j] = b1[j] + wih1[j][0] * h0[0] + wih1[j][1] * h0[1] + wih1[j][2] * h0[2]
                         + whh1[j][0] * h1[0] + whh1[j][1] * h1[1] + whh1[j][2] * h1[2];
#pragma unroll
        for (int u = 0; u < 3; u++) {
            c1[u] = fsigm(g[3 + u]) * c1[u] + fsigm(g[u]) * ftanh(g[6 + u]);
            h1[u] = fsigm(g[9 + u]) * ftanh(c1[u]);
        }
        float m = fmaxf(h1[0], fmaxf(h1[1], h1[2]));
        float e0 = __expf(h1[0] - m), e1 = __expf(h1[1] - m), e2 = __expf(h1[2] - m);
        float inv = __fdividef(1.0f, e0 + e1 + e2);
        al[t * KK + 0] = e0 * inv;
        al[t * KK + 1] = e1 * inv;
        al[t * KK + 2] = e2 * inv;
    }
}

// ---------------- Kernel B: forward Kalman filter ----------------
// P0 store prefetched mix | P1 r,M1,M1T | P2 S,WT,HT,w | P3 GJ16 (warp0 serial) |
// P45 prefetch-issue + V,Kg,G (syncwarp) + updates (intra-warp).  5 barriers.
__global__ void __launch_bounds__(256) fwd_kernel(const float* __restrict__ a,
                                                  const float* __restrict__ A,
                                                  const float* __restrict__ C,
                                                  const float* __restrict__ R,
                                                  const float* __restrict__ Q,
                                                  const float* __restrict__ mu0,
                                                  const float* __restrict__ sigma0) {
    const int b = blockIdx.x;
    const int tid = threadIdx.x;
    const int i8 = tid >> 3;
    const int q4 = (tid & 7) * 4;
    const int jj = (tid & 7) * 2;

    __shared__ __align__(16) float sAt[DZ][36];
    __shared__ __align__(16) float sCt[DA][36];
    __shared__ __align__(16) float sCtT[DZ][20];
    __shared__ __align__(16) float sSigP[DZ][36], sQ[DZ][36];
    __shared__ __align__(16) float sWT[DZ][36];
    __shared__ __align__(16) float sM1[DZ][20], sKg[DZ][20], sG[DZ][20];
    __shared__ __align__(16) float sM1T[DA][36], sHT[DA][36];
    __shared__ __align__(16) float sS[DA][20];
    __shared__ float sR[DA][17];
    __shared__ float smu_f[DZ], smu_p[DZ], sw[DZ], sr[DA];

    float4 pA = make_float4(0, 0, 0, 0), pC = make_float4(0, 0, 0, 0);

    if (tid < DZ) { smu_f[tid] = mu0[tid]; smu_p[tid] = mu0[tid]; }
    {
        int e = tid * 4, ii = e >> 5, jc = e & 31;
        *(float4*)&sSigP[ii][jc] = ((const float4*)sigma0)[tid];
        *(float4*)&sQ[ii][jc]    = ((const float4*)Q)[tid];
        sR[tid >> 4][tid & 15] = R[tid];
    }
    // prologue: mix t=0 into prefetch regs
    {
        const size_t ab = (size_t)b * TT * KK;
        const float a0 = g_alpha[ab + 0], a1 = g_alpha[ab + 1], a2 = g_alpha[ab + 2];
        const float4* A0 = (const float4*)A;
        const float4* A1 = A0 + (size_t)TT * 256;
        const float4* A2 = A1 + (size_t)TT * 256;
        float4 v0 = A0[tid], v1 = A1[tid], v2 = A2[tid];
        pA.x = a0 * v0.x + a1 * v1.x + a2 * v2.x;
        pA.y = a0 * v0.y + a1 * v1.y + a2 * v2.y;
        pA.z = a0 * v0.z + a1 * v1.z + a2 * v2.z;
        pA.w = a0 * v0.w + a1 * v1.w + a2 * v2.w;
        if (tid < 128) {
            const float4* C0 = (const float4*)C;
            const float4* C1 = C0 + (size_t)TT * 128;
            const float4* C2 = C1 + (size_t)TT * 128;
            float4 w0 = C0[tid], w1 = C1[tid], w2 = C2[tid];
            pC.x = a0 * w0.x + a1 * w1.x + a2 * w2.x;
            pC.y = a0 * w0.y + a1 * w1.y + a2 * w2.y;
            pC.z = a0 * w0.z + a1 * w1.z + a2 * w2.z;
            pC.w = a0 * w0.w + a1 * w1.w + a2 * w2.w;
        }
    }
    __syncthreads();

    for (int t = 0; t < TT; t++) {
        // P0: commit prefetched mixed At/Ct to smem (+ CtT transpose)
        {
            int e = tid * 4, ii = e >> 5, jc = e & 31;
            *(float4*)&sAt[ii][jc] = pA;
            if (tid < 128) {
                int ec = tid * 4, ic = ec >> 5, jcc = ec & 31;
                *(float4*)&sCt[ic][jcc] = pC;
                sCtT[jcc + 0][ic] = pC.x; sCtT[jcc + 1][ic] = pC.y;
                sCtT[jcc + 2][ic] = pC.z; sCtT[jcc + 3][ic] = pC.w;
            }
        }
        __syncthreads();

        // P1: r = a - Ct mu_f ; M1 = sigP * CtT (+ M1T)
        if (tid < DA) {
            float s = a[((size_t)b * TT + t) * DA + tid];
#pragma unroll
            for (int j = 0; j < DZ; j++) s -= sCt[tid][j] * smu_f[j];
            sr[tid] = s;
        }
        {
            float s0 = 0.f, s1 = 0.f;
#pragma unroll
            for (int k = 0; k < DZ; k++) {
                float av = sSigP[i8][k];
                s0 += av * sCtT[k][jj];
                s1 += av * sCtT[k][jj + 1];
            }
            sM1[i8][jj] = s0; sM1[i8][jj + 1] = s1;
            sM1T[jj][i8] = s0; sM1T[jj + 1][i8] = s1;
        }
        __syncthreads();

        // P2: S = Ct*M1 + R ; WT = (At*sigP)^T ; HT = (At*M1)^T ; w = At*mu_p
        {
            {
                int i = tid >> 4, j = tid & 15;
                float s = sR[i][j];
#pragma unroll
                for (int k = 0; k < DZ; k++) s += sCt[i][k] * sM1[k][j];
                sS[i][j] = s;
            }
            {
                float4 acc = make_float4(0, 0, 0, 0);
#pragma unroll
                for (int k = 0; k < DZ; k++) {
                    float av = sAt[i8][k];
                    float4 bv = *(const float4*)&sSigP[k][q4];
                    acc.x += av * bv.x; acc.y += av * bv.y;
                    acc.z += av * bv.z; acc.w += av * bv.w;
                }
                sWT[q4 + 0][i8] = acc.x; sWT[q4 + 1][i8] = acc.y;
                sWT[q4 + 2][i8] = acc.z; sWT[q4 + 3][i8] = acc.w;
            }
#pragma unroll
            for (int rep = 0; rep < 2; rep++) {
                int u = tid + rep * 256;
                int i = u >> 4, j = u & 15;
                float h = 0.f;
#pragma unroll
                for (int k = 0; k < DZ; k++) h += sAt[i][k] * sM1[k][j];
                sHT[j][i] = h;
            }
            if (tid < DZ) {
                float s = 0.f;
#pragma unroll
                for (int k = 0; k < DZ; k++) s += sAt[tid][k] * smu_p[k];
                sw[tid] = s;
            }
        }
        __syncthreads();

        // P3: warp 0 inverts S in place (serial)
        if (tid < 32) warp_gj_reg<DA, 20>(&sS[0][0], tid);
        __syncthreads();

        // P45: prefetch-issue t+1 ; V,Kg,G ; syncwarp ; sig/mu updates (intra-warp)
        {
            if (t + 1 < TT) {
                const size_t ab2 = ((size_t)b * TT + (t + 1)) * KK;
                const float na0 = g_alpha[ab2 + 0];
                const float na1 = g_alpha[ab2 + 1];
                const float na2 = g_alpha[ab2 + 2];
                const float4* A0 = (const float4*)A + (size_t)(t + 1) * 256;
                const float4* A1 = A0 + (size_t)TT * 256;
                const float4* A2 = A1 + (size_t)TT * 256;
                float4 v0 = A0[tid], v1 = A1[tid], v2 = A2[tid];
                pA.x = na0 * v0.x + na1 * v1.x + na2 * v2.x;
                pA.y = na0 * v0.y + na1 * v1.y + na2 * v2.y;
                pA.z = na0 * v0.z + na1 * v1.z + na2 * v2.z;
                pA.w = na0 * v0.w + na1 * v1.w + na2 * v2.w;
                if (tid < 128) {
                    const float4* C0 = (const float4*)C + (size_t)(t + 1) * 128;
                    const float4* C1 = C0 + (size_t)TT * 128;
                    const float4* C2 = C1 + (size_t)TT * 128;
                    float4 w0 = C0[tid], w1 = C1[tid], w2 = C2[tid];
                    pC.x = na0 * w0.x + na1 * w1.x + na2 * w2.x;
                    pC.y = na0 * w0.y + na1 * w1.y + na2 * w2.y;
                    pC.z = na0 * w0.z + na1 * w1.z + na2 * w2.z;
                    pC.w = na0 * w0.w + na1 * w1.w + na2 * w2.w;
                }
            }

            // Kg row i8 cols jj,jj+1 ; G likewise (kept in regs too)
            float k0 = 0.f, k1 = 0.f, g0 = 0.f, g1 = 0.f;
#pragma unroll
            for (int k = 0; k < DA; k++) {
                float m = sM1[i8][k];
                float h = sHT[k][i8];
                float s0 = sS[k][jj], s1 = sS[k][jj + 1];
                k0 += m * s0; k1 += m * s1;
                g0 += h * s0; g1 += h * s1;
            }
            sKg[i8][jj] = k0; sKg[i8][jj + 1] = k1;
            sG[i8][jj]  = g0; sG[i8][jj + 1]  = g1;
            __syncwarp();

            const size_t sb = (size_t)t * BSZ + b;

            // sigN = sigP - Kg*M1T ; sigP' = (Q + At*WT) - G*HT
            float4 accN = *(const float4*)&sSigP[i8][q4];
            float4 accP = *(const float4*)&sQ[i8][q4];
#pragma unroll
            for (int k = 0; k < DZ; k++) {
                float av = sAt[i8][k];
                float4 bv = *(const float4*)&sWT[k][q4];
                accP.x += av * bv.x; accP.y += av * bv.y;
                accP.z += av * bv.z; accP.w += av * bv.w;
            }
#pragma unroll
            for (int k = 0; k < DA; k++) {
                float kg = sKg[i8][k];
                float gg = sG[i8][k];
                float4 m = *(const float4*)&sM1T[k][q4];
                float4 h = *(const float4*)&sHT[k][q4];
                accN.x -= kg * m.x; accN.y -= kg * m.y;
                accN.z -= kg * m.z; accN.w -= kg * m.w;
                accP.x -= gg * h.x; accP.y -= gg * h.y;
                accP.z -= gg * h.z; accP.w -= gg * h.w;
            }
            *(float4*)&g_sigf[sb * (DZ * DZ) + i8 * DZ + q4] = accN;
            *(float4*)&sSigP[i8][q4] = accP;
            *(float4*)&g_sigp[sb * (DZ * DZ) + i8 * DZ + q4] = accP;

            // mu updates via 8-lane subgroup reduction (row i8 within warp)
            float pm = k0 * sr[jj] + k1 * sr[jj + 1];
            float pg = g0 * sr[jj] + g1 * sr[jj + 1];
#pragma unroll
            for (int o = 4; o >= 1; o >>= 1) {
                pm += __shfl_down_sync(0xffffffffu, pm, o);
                pg += __shfl_down_sync(0xffffffffu, pg, o);
            }
            if ((tid & 7) == 0) {
                float mn = smu_p[i8] + pm;
                float mp = sw[i8] + pg;
                smu_f[i8] = mn; g_muf[sb * DZ + i8] = mn;
                smu_p[i8] = mp; g_mup[sb * DZ + i8] = mp;
            }
        }
        __syncthreads();
    }
}

// ---------------- Kernel I: batch-parallel inversion of all sigp_t ----------
__global__ void __launch_bounds__(256) inv_kernel() {
    const int w = blockIdx.x * (blockDim.x >> 5) + (threadIdx.x >> 5);
    if (w >= TT * BSZ) return;
    const int lane = threadIdx.x & 31;

    const float4* src = (const float4*)(g_sigp + (size_t)w * (DZ * DZ));
    float c[DZ];
#pragma unroll
    for (int s = 0; s < 8; s++) {
        float4 v = src[lane * 8 + s];
        c[s * 4 + 0] = v.x; c[s * 4 + 1] = v.y;
        c[s * 4 + 2] = v.z; c[s * 4 + 3] = v.w;
    }
    float dinv = 1.0f;
#pragma unroll
    for (int p = 0; p < DZ; p++) {
        float pv = __shfl_sync(0xffffffffu, c[p], p);
        float rpv = __fdividef(1.0f, pv);
        float f = (lane == p) ? 0.0f : c[p] * rpv;
        if (lane == p) dinv = rpv;
        float ncp = (lane == p) ? 1.0f : -f;
#pragma unroll
        for (int j = 0; j < DZ; j++)
            if (j != p) c[j] -= f * __shfl_sync(0xffffffffu, c[j], p);
        c[p] = ncp;
    }
    float4* dst = (float4*)(g_pinv + (size_t)w * (DZ * DZ));
#pragma unroll
    for (int s = 0; s < 8; s++) {
        float4 v;
        v.x = c[s * 4 + 0] * dinv; v.y = c[s * 4 + 1] * dinv;
        v.z = c[s * 4 + 2] * dinv; v.w = c[s * 4 + 3] * dinv;
        dst[lane * 8 + s] = v;
    }
}

// ---------------- Kernel C: RTS backward smoother (no inversions, pipelined) --
// P1 prefetch-issue + U,X,xv | P2 outputs | P0' commit prefetch + D,muD.
__global__ void __launch_bounds__(256) bwd_kernel(const float* __restrict__ A,
                                                  float* __restrict__ out) {
    const int b = blockIdx.x;
    const int tid = threadIdx.x;
    const int i8 = tid >> 3;
    const int q4 = (tid & 7) * 4;

    __shared__ __align__(16) float sAT[DZ][36];
    __shared__ __align__(16) float sSigF[DZ][36], sSigNc[DZ][36], sD[DZ][36];
    __shared__ __align__(16) float sU[DZ][36], sX[DZ][36], sPinv[DZ][36];
    __shared__ float sMuN[DZ], sMuD[DZ], sxv[DZ];

    float4 pAT = make_float4(0, 0, 0, 0);
    float4 pSF = make_float4(0, 0, 0, 0);
    float4 pPI = make_float4(0, 0, 0, 0);
    float4 pSP = make_float4(0, 0, 0, 0);
    float pMUP = 0.f;

    // prologue: t = TT-1 outputs + carry ; load t = TT-2 inputs directly
    {
        size_t sb = ((size_t)(TT - 1) * BSZ + b);
        size_t ob = ((size_t)b * TT + (TT - 1)) * (DZ + DZ * DZ);
        int e = tid * 4, ii = e >> 5, jj = e & 31;
        float4 v = ((const float4*)(g_sigf + sb * (DZ * DZ)))[tid];
        *(float4*)&sSigNc[ii][jj] = v;
        *(float4*)&out[ob + DZ + e] = v;
        if (tid < DZ) {
            float m = g_muf[sb * DZ + tid];
            sMuN[tid] = m;
            out[ob + tid] = m;
        }
        const int t0 = TT - 2;
        const size_t sb2 = (size_t)t0 * BSZ + b;
        const size_t ab = ((size_t)b * TT + (t0 + 1)) * KK;
        const float a0 = g_alpha[ab + 0], a1 = g_alpha[ab + 1], a2 = g_alpha[ab + 2];
        const float4* A0 = (const float4*)A + (size_t)(t0 + 1) * 256;
        const float4* A1 = A0 + (size_t)TT * 256;
        const float4* A2 = A1 + (size_t)TT * 256;
        float4 v0 = A0[tid], v1 = A1[tid], v2 = A2[tid];
        sAT[jj + 0][ii] = a0 * v0.x + a1 * v1.x + a2 * v2.x;
        sAT[jj + 1][ii] = a0 * v0.y + a1 * v1.y + a2 * v2.y;
        sAT[jj + 2][ii] = a0 * v0.z + a1 * v1.z + a2 * v2.z;
        sAT[jj + 3][ii] = a0 * v0.w + a1 * v1.w + a2 * v2.w;
        *(float4*)&sSigF[ii][jj] = ((const float4*)(g_sigf + sb2 * (DZ * DZ)))[tid];
        *(float4*)&sPinv[ii][jj] = ((const float4*)(g_pinv + sb2 * (DZ * DZ)))[tid];
        float4 sp = ((const float4*)(g_sigp + sb2 * (DZ * DZ)))[tid];
        float4 n = make_float4(sSigNc[ii][jj + 0], sSigNc[ii][jj + 1],
                               sSigNc[ii][jj + 2], sSigNc[ii][jj + 3]);
        // NOTE: sSigNc row ii just written by this thread; other rows not needed
        float4 d = make_float4(n.x - sp.x, n.y - sp.y, n.z - sp.z, n.w - sp.w);
        *(float4*)&sD[ii][jj] = d;
        if (tid < DZ) sMuD[tid] = sMuN[tid] - g_mup[sb2 * DZ + tid];
    }
    __syncthreads();

    for (int t = TT - 2; t >= 0; t--) {
        const size_t sb = (size_t)t * BSZ + b;

        // P1: issue prefetch for t-1 ; compute U = sigF*AT, X = Pinv*D, xv
        if (t > 0) {
            const int t2 = t - 1;
            const size_t sb2 = (size_t)t2 * BSZ + b;
            const size_t ab2 = ((size_t)b * TT + (t2 + 1)) * KK;
            const float na0 = g_alpha[ab2 + 0];
            const float na1 = g_alpha[ab2 + 1];
            const float na2 = g_alpha[ab2 + 2];
            const float4* A0 = (const float4*)A + (size_t)(t2 + 1) * 256;
            const float4* A1 = A0 + (size_t)TT * 256;
            const float4* A2 = A1 + (size_t)TT * 256;
            float4 v0 = A0[tid], v1 = A1[tid], v2 = A2[tid];
            pAT.x = na0 * v0.x + na1 * v1.x + na2 * v2.x;
            pAT.y = na0 * v0.y + na1 * v1.y + na2 * v2.y;
            pAT.z = na0 * v0.z + na1 * v1.z + na2 * v2.z;
            pAT.w = na0 * v0.w + na1 * v1.w + na2 * v2.w;
            pSF = ((const float4*)(g_sigf + sb2 * (DZ * DZ)))[tid];
            pPI = ((const float4*)(g_pinv + sb2 * (DZ * DZ)))[tid];
            pSP = ((const float4*)(g_sigp + sb2 * (DZ * DZ)))[tid];
            if (tid < DZ) pMUP = g_mup[sb2 * DZ + tid];
        }
        {
            float4 au = make_float4(0, 0, 0, 0);
            float4 ax = make_float4(0, 0, 0, 0);
#pragma unroll
            for (int k = 0; k < DZ; k++) {
                float fu = sSigF[i8][k];
                float fx = sPinv[i8][k];
                float4 bu = *(const float4*)&sAT[k][q4];
                float4 bx = *(const float4*)&sD[k][q4];
                au.x += fu * bu.x; au.y += fu * bu.y;
                au.z += fu * bu.z; au.w += fu * bu.w;
                ax.x += fx * bx.x; ax.y += fx * bx.y;
                ax.z += fx * bx.z; ax.w += fx * bx.w;
            }
            *(float4*)&sU[i8][q4] = au;
            *(float4*)&sX[i8][q4] = ax;
            if (tid < DZ) {
                float s = 0.f;
#pragma unroll
                for (int k = 0; k < DZ; k++) s += sPinv[tid][k] * sMuD[k];
                sxv[tid] = s;
            }
        }
        __syncthreads();

        // P2: sigS = sigF + U*X -> out + carry ; muS = muF + U*xv -> out + carry
        {
            const size_t ob = ((size_t)b * TT + t) * (DZ + DZ * DZ);
            float4 acc = *(const float4*)&sSigF[i8][q4];
#pragma unroll
            for (int k = 0; k < DZ; k++) {
                float av = sU[i8][k];
                float4 bv = *(const float4*)&sX[k][q4];
                acc.x += av * bv.x; acc.y += av * bv.y;
                acc.z += av * bv.z; acc.w += av * bv.w;
            }
            *(float4*)&sSigNc[i8][q4] = acc;
            *(float4*)&out[ob + DZ + i8 * DZ + q4] = acc;
            if (tid < DZ) {
                float s = g_muf[sb * DZ + tid];
#pragma unroll
                for (int k = 0; k < DZ; k++) s += sU[tid][k] * sxv[k];
                sMuN[tid] = s;
                out[ob + tid] = s;
            }
        }
        __syncthreads();

        // P0': commit prefetched inputs for t-1 ; D = sigNc - sigp ; muD
        if (t > 0) {
            int e = tid * 4, ii = e >> 5, jj = e & 31;
            sAT[jj + 0][ii] = pAT.x; sAT[jj + 1][ii] = pAT.y;
            sAT[jj + 2][ii] = pAT.z; sAT[jj + 3][ii] = pAT.w;
            *(float4*)&sSigF[ii][jj] = pSF;
            *(float4*)&sPinv[ii][jj] = pPI;
            float4 n = *(const float4*)&sSigNc[ii][jj];
            float4 d = make_float4(n.x - pSP.x, n.y - pSP.y, n.z - pSP.z, n.w - pSP.w);
            *(float4*)&sD[ii][jj] = d;
            if (tid < DZ) sMuD[tid] = sMuN[tid] - pMUP;
            __syncthreads();
        }
    }
}

// ---------------- launch ----------------
extern "C" void kernel_launch(void* const* d_in, const int* in_sizes, int n_in,
                              void* d_out, int out_size) {
    const float* a      = (const float*)d_in[0];
    const float* A      = (const float*)d_in[1];
    const float* C      = (const float*)d_in[2];
    const float* R      = (const float*)d_in[3];
    const float* Q      = (const float*)d_in[4];
    const float* mu0    = (const float*)d_in[5];
    const float* sigma0 = (const float*)d_in[6];
    const float* Wih0   = (const float*)d_in[7];
    const float* Whh0   = (const float*)d_in[8];
    const float* bih0   = (const float*)d_in[9];
    const float* bhh0   = (const float*)d_in[10];
    const float* Wih1   = (const float*)d_in[11];
    const float* Whh1   = (const float*)d_in[12];
    const float* bih1   = (const float*)d_in[13];
    const float* bhh1   = (const float*)d_in[14];
    float* out = (float*)d_out;

    int n0 = BSZ * TT * GG;
    xw0_kernel<<<(n0 + 255) / 256, 256>>>(a, Wih0, bih0, bhh0);
    lstm_kernel<<<1, 64>>>(Whh0, Wih1, Whh1, bih1, bhh1);
    fwd_kernel<<<BSZ, 256>>>(a, A, C, R, Q, mu0, sigma0);
    inv_kernel<<<(TT * BSZ) / 8, 256>>>();
    bwd_kernel<<<BSZ, 256>>>(A, out);
}